// round 1
// baseline (speedup 1.0000x reference)
#include <cuda_runtime.h>

// ---------------- problem constants ----------------
namespace {
constexpr int CB  = 4;      // batch
constexpr int CS  = 1024;   // seq
constexpr int CD  = 1280;   // model dim
constexpr int CH  = 16;     // heads
constexpr int CHD = 80;     // head dim
constexpr int CM  = CB * CS;          // 4096 rows
constexpr int CNQKV = 3 * CD;         // 3840
}
#define ATTN_SCALE 0.11180339887498948f  // 80^-0.5

// ---------------- scratch (device globals; no allocs allowed) ----------------
__device__ float g_q[CB * CH * CS * CHD];     // [b,h,s,d]
__device__ float g_k[CB * CH * CS * CHD];
__device__ float g_v[CB * CH * CS * CHD];
__device__ float g_ctx[CM * CD];              // [b,s, h*HD+d]

// ============================================================================
// Tiled fp32 GEMM: C(64x64 tile) = A(M x K) * W(K x N) + bias
// MODE 0: A = x, write scattered into g_q/g_k/g_v  (QKV projection)
// MODE 1: A = g_ctx, write to out (output projection)
// 256 threads, BM=BN=64, BK=16, 4x4 per-thread microtile.
// A tile stored k-major (transposed) in smem so both operands read as LDS.128.
// ============================================================================
template <int MODE>
__global__ void __launch_bounds__(256)
gemm64(const float* __restrict__ A, const float* __restrict__ W,
       const float* __restrict__ bias, float* __restrict__ out,
       int N, int K)
{
    __shared__ float As[16 * 68];   // [k][m], pitch 68 (16B-aligned rows, bank-spread)
    __shared__ float Bs[16 * 64];   // [k][n]

    const float* __restrict__ Aeff = (MODE == 1) ? (const float*)g_ctx : A;

    const int tid = threadIdx.x;
    const int tx  = tid & 15;       // n microtile
    const int ty  = tid >> 4;       // m microtile
    const int m0  = blockIdx.y * 64;
    const int n0  = blockIdx.x * 64;

    const int lr = tid >> 4;        // A-load row within tile (0..15, x4 passes)
    const int lc = tid & 15;        // A-load k
    const int br = tid >> 6;        // B-load k (0..3, x4 passes)
    const int bc = tid & 63;        // B-load n

    float acc[4][4] = {};

    for (int k0 = 0; k0 < K; k0 += 16) {
        #pragma unroll
        for (int i = 0; i < 4; i++) {
            int m = lr + 16 * i;
            As[lc * 68 + m] = Aeff[(size_t)(m0 + m) * K + k0 + lc];
        }
        #pragma unroll
        for (int i = 0; i < 4; i++) {
            int kk = br + 4 * i;
            Bs[kk * 64 + bc] = W[(size_t)(k0 + kk) * N + n0 + bc];
        }
        __syncthreads();

        #pragma unroll
        for (int k = 0; k < 16; k++) {
            float4 a4 = *reinterpret_cast<const float4*>(&As[k * 68 + ty * 4]);
            float4 b4 = *reinterpret_cast<const float4*>(&Bs[k * 64 + tx * 4]);
            float a[4] = {a4.x, a4.y, a4.z, a4.w};
            float b[4] = {b4.x, b4.y, b4.z, b4.w};
            #pragma unroll
            for (int i = 0; i < 4; i++)
                #pragma unroll
                for (int j = 0; j < 4; j++)
                    acc[i][j] += a[i] * b[j];
        }
        __syncthreads();
    }

    #pragma unroll
    for (int i = 0; i < 4; i++) {
        const int m = m0 + ty * 4 + i;
        const int b = m >> 10;          // /1024
        const int s = m & 1023;
        #pragma unroll
        for (int j = 0; j < 4; j++) {
            const int n = n0 + tx * 4 + j;
            float v = acc[i][j] + bias[n];
            if (MODE == 0) {
                const int which = n / CD;          // 0=q 1=k 2=v
                const int r = n - which * CD;
                const int h = r / CHD;
                const int d = r - h * CHD;
                const size_t di = ((size_t)(b * CH + h) * CS + s) * CHD + d;
                if (which == 0)      g_q[di] = v;
                else if (which == 1) g_k[di] = v;
                else                 g_v[di] = v;
            } else {
                out[(size_t)m * CD + n] = v;
            }
        }
    }
}

// ============================================================================
// RoPE (half-rotation): one thread per (b,h,s, d<40) pair; applies to q and k.
// cos/sin are [S, 80] with the two 40-halves identical.
// ============================================================================
__global__ void __launch_bounds__(256)
rope_kernel(const float* __restrict__ cosb, const float* __restrict__ sinb)
{
    const int idx = blockIdx.x * blockDim.x + threadIdx.x;
    constexpr int TOT = CB * CH * CS * (CHD / 2);
    if (idx >= TOT) return;
    const int d  = idx % (CHD / 2);
    const int s  = (idx / (CHD / 2)) % CS;
    const int bh = idx / ((CHD / 2) * CS);

    const float c  = cosb[s * CHD + d];
    const float sn = sinb[s * CHD + d];
    const size_t base = ((size_t)bh * CS + s) * CHD;

    float q1 = g_q[base + d], q2 = g_q[base + d + 40];
    g_q[base + d]      = q1 * c - q2 * sn;
    g_q[base + d + 40] = q2 * c + q1 * sn;

    float k1 = g_k[base + d], k2 = g_k[base + d + 40];
    g_k[base + d]      = k1 * c - k2 * sn;
    g_k[base + d + 40] = k2 * c + k1 * sn;
}

// ============================================================================
// Fused flash attention (fp32): grid (S/64, B*H), 256 threads.
// Q tile 64x80 resident (d-major in smem), stream K/V in 64-row tiles,
// online softmax, P staged through smem, O accum in registers (4 rows x 5 cols
// per thread). Writes g_ctx[b, s, h*80+d].
// ============================================================================
__global__ void __launch_bounds__(256)
attn_kernel()
{
    extern __shared__ float sm[];
    float* Qt = sm;                        // [80][68]  d-major, *SCALE applied
    float* Kt = Qt + 80 * 68;              // [80][68]  d-major
    float* Vs = Kt + 80 * 68;              // [64][81]  row-major
    float* Ps = Vs + 64 * 81;              // [64][68]

    const int tid = threadIdx.x;
    const int tx  = tid & 15;
    const int ty  = tid >> 4;
    const int bh  = blockIdx.y;
    const int q0  = blockIdx.x * 64;

    const float* __restrict__ Qg = g_q + (size_t)bh * CS * CHD;
    const float* __restrict__ Kg = g_k + (size_t)bh * CS * CHD;
    const float* __restrict__ Vg = g_v + (size_t)bh * CS * CHD;

    // load Q tile transposed (scaled)
    for (int p = tid; p < 64 * CHD; p += 256) {
        const int r = p / CHD, c = p - r * CHD;
        Qt[c * 68 + r] = Qg[(size_t)(q0 + r) * CHD + c] * ATTN_SCALE;
    }

    float m_[4], l_[4], o_[4][5];
    #pragma unroll
    for (int i = 0; i < 4; i++) {
        m_[i] = -1e30f; l_[i] = 0.f;
        #pragma unroll
        for (int c = 0; c < 5; c++) o_[i][c] = 0.f;
    }

    for (int t = 0; t < CS; t += 64) {
        __syncthreads();   // prev PV done (and Q load on first iter ordering)
        for (int p = tid; p < 64 * CHD; p += 256) {
            const int r = p / CHD, c = p - r * CHD;
            Kt[c * 68 + r]  = Kg[(size_t)(t + r) * CHD + c];
            Vs[r * 81 + c]  = Vg[(size_t)(t + r) * CHD + c];
        }
        __syncthreads();

        // S = Q K^T  (scaled), 4x4 per thread
        float sacc[4][4] = {};
        #pragma unroll 8
        for (int d = 0; d < CHD; d++) {
            float4 a4 = *reinterpret_cast<const float4*>(&Qt[d * 68 + ty * 4]);
            float4 b4 = *reinterpret_cast<const float4*>(&Kt[d * 68 + tx * 4]);
            float a[4] = {a4.x, a4.y, a4.z, a4.w};
            float b[4] = {b4.x, b4.y, b4.z, b4.w};
            #pragma unroll
            for (int i = 0; i < 4; i++)
                #pragma unroll
                for (int j = 0; j < 4; j++)
                    sacc[i][j] += a[i] * b[j];
        }

        // online softmax (rows = ty*4+i; reduce across the 16 tx lanes)
        #pragma unroll
        for (int i = 0; i < 4; i++) {
            float mx = fmaxf(fmaxf(sacc[i][0], sacc[i][1]),
                             fmaxf(sacc[i][2], sacc[i][3]));
            #pragma unroll
            for (int off = 8; off >= 1; off >>= 1)
                mx = fmaxf(mx, __shfl_xor_sync(0xffffffffu, mx, off));
            const float mnew = fmaxf(m_[i], mx);
            const float alpha = __expf(m_[i] - mnew);
            float rs = 0.f;
            #pragma unroll
            for (int j = 0; j < 4; j++) {
                const float p = __expf(sacc[i][j] - mnew);
                sacc[i][j] = p;
                rs += p;
            }
            #pragma unroll
            for (int off = 8; off >= 1; off >>= 1)
                rs += __shfl_xor_sync(0xffffffffu, rs, off);
            l_[i] = l_[i] * alpha + rs;
            m_[i] = mnew;
            #pragma unroll
            for (int c = 0; c < 5; c++) o_[i][c] *= alpha;
            float4 pv = make_float4(sacc[i][0], sacc[i][1], sacc[i][2], sacc[i][3]);
            *reinterpret_cast<float4*>(&Ps[(ty * 4 + i) * 68 + tx * 4]) = pv;
        }
        __syncthreads();

        // O += P @ V   (rows ty*4+i, cols tx*5+c)
        #pragma unroll 4
        for (int j = 0; j < 64; j++) {
            float pr[4], vv[5];
            #pragma unroll
            for (int i = 0; i < 4; i++) pr[i] = Ps[(ty * 4 + i) * 68 + j];
            #pragma unroll
            for (int c = 0; c < 5; c++) vv[c] = Vs[j * 81 + tx * 5 + c];
            #pragma unroll
            for (int i = 0; i < 4; i++)
                #pragma unroll
                for (int c = 0; c < 5; c++)
                    o_[i][c] += pr[i] * vv[c];
        }
    }

    // epilogue: normalize and write ctx[b, s, h*80 + d]
    const int b = bh / CH, h = bh - b * CH;
    #pragma unroll
    for (int i = 0; i < 4; i++) {
        const int srow = q0 + ty * 4 + i;
        const float inv = 1.f / l_[i];
        #pragma unroll
        for (int c = 0; c < 5; c++)
            g_ctx[((size_t)b * CS + srow) * CD + h * CHD + tx * 5 + c] = o_[i][c] * inv;
    }
}

// ============================================================================
// launch
// ============================================================================
extern "C" void kernel_launch(void* const* d_in, const int* in_sizes, int n_in,
                              void* d_out, int out_size)
{
    const float* x        = (const float*)d_in[0];
    const float* rope_cos = (const float*)d_in[1];
    const float* rope_sin = (const float*)d_in[2];
    const float* Wqkv     = (const float*)d_in[3];
    const float* bqkv     = (const float*)d_in[4];
    const float* Wproj    = (const float*)d_in[5];
    const float* bproj    = (const float*)d_in[6];
    float* out            = (float*)d_out;

    // 1) QKV projection + bias, scattered into per-head q/k/v
    gemm64<0><<<dim3(CNQKV / 64, CM / 64), 256>>>(x, Wqkv, bqkv, nullptr, CNQKV, CD);

    // 2) RoPE on q,k
    {
        const int pairs = CB * CH * CS * (CHD / 2);
        rope_kernel<<<(pairs + 255) / 256, 256>>>(rope_cos, rope_sin);
    }

    // 3) fused flash attention -> g_ctx
    {
        const int smem = (80 * 68 * 2 + 64 * 81 + 64 * 68) * (int)sizeof(float); // 81,664 B
        cudaFuncSetAttribute(attn_kernel, cudaFuncAttributeMaxDynamicSharedMemorySize, smem);
        attn_kernel<<<dim3(CS / 64, CB * CH), 256, smem>>>();
    }

    // 4) output projection + bias -> d_out
    gemm64<1><<<dim3(CD / 64, CM / 64), 256>>>(nullptr, Wproj, bproj, out, CD, CD);
}

// round 4
// speedup vs baseline: 1.7134x; 1.7134x over previous
#include <cuda_runtime.h>
#include <cstdint>

// ---------------- problem constants ----------------
namespace {
constexpr int CB  = 4;      // batch
constexpr int CS  = 1024;   // seq
constexpr int CD  = 1280;   // model dim
constexpr int CH  = 16;     // heads
constexpr int CHD = 80;     // head dim
constexpr int CM  = CB * CS;          // 4096 rows
constexpr int CNQKV = 3 * CD;         // 3840

// GEMM tiling
constexpr int BM = 128, BN = 128, BK = 32;
constexpr int PA = 36;    // A smem pitch (floats): 4g+t conflict-free
constexpr int PB = 136;   // B smem pitch (floats): 8t+g conflict-free
constexpr int ASZ = BM * PA;          // 4608 floats
constexpr int BSZ = BK * PB;          // 4352 floats
constexpr int STG = ASZ + BSZ;        // stage stride (floats) = 8960
constexpr int GEMM_SMEM = 2 * STG * 4;  // 71680 bytes
}
#define ATTN_SCALE 0.11180339887498948f  // 80^-0.5

// ---------------- scratch (device globals; no allocs allowed) ----------------
__device__ __align__(16) float g_q[CB * CH * CS * CHD];     // [b,h,s,d]
__device__ __align__(16) float g_k[CB * CH * CS * CHD];
__device__ __align__(16) float g_v[CB * CH * CS * CHD];
__device__ __align__(16) float g_ctx[CM * CD];              // [b,s, h*HD+d]

// ---------------- tf32 helpers (plain sm_103-safe PTX) ----------------
__device__ __forceinline__ uint32_t f2tf32(float f) {
    uint32_t u;
    asm("cvt.rna.tf32.f32 %0, %1;" : "=r"(u) : "f"(f));
    return u;
}
__device__ __forceinline__ void mma_tf32(float c[4],
                                         uint32_t a0, uint32_t a1, uint32_t a2, uint32_t a3,
                                         uint32_t b0, uint32_t b1) {
    asm volatile(
        "mma.sync.aligned.m16n8k8.row.col.f32.tf32.tf32.f32 "
        "{%0,%1,%2,%3}, {%4,%5,%6,%7}, {%8,%9}, {%0,%1,%2,%3};"
        : "+f"(c[0]), "+f"(c[1]), "+f"(c[2]), "+f"(c[3])
        : "r"(a0), "r"(a1), "r"(a2), "r"(a3), "r"(b0), "r"(b1));
}

// ============================================================================
// tf32 mma.sync GEMM: C(128x128 tile) = A(MxK) @ W(KxN) + bias
// MODE 0: A = x, scatter epilogue into g_q/g_k/g_v
// MODE 1: A = g_ctx, write to out
// 256 threads (8 warps, 2x4), warp tile 64x32 (4x4 m16n8k8 atoms), BK=32,
// register-prefetch double buffering with cvt.rna at STS time.
// A tile: 128 rows x 32 k  -> per pass: m = f>>3 (0..127), kq = f&7 (x4 floats)
// B tile:  32 krows x 128 n -> per pass: kk = f>>5 (0..31), nq = f&31 (x4 floats)
// ============================================================================
template <int MODE>
__global__ void __launch_bounds__(256)
gemm_tc(const float* __restrict__ A, const float* __restrict__ W,
        const float* __restrict__ bias, float* __restrict__ out,
        int N, int K)
{
    extern __shared__ float sm[];

    const float* __restrict__ Aeff = (MODE == 1) ? (const float*)g_ctx : A;

    const int tid  = threadIdx.x;
    const int wid  = tid >> 5;
    const int lane = tid & 31;
    const int g    = lane >> 2;      // 0..7
    const int t    = lane & 3;       // 0..3
    const int wm   = wid & 1;        // 2 warp rows  (64 m each)
    const int wn   = wid >> 1;       // 4 warp cols  (32 n each)
    const int m0   = blockIdx.y * BM;
    const int n0   = blockIdx.x * BN;

    float cf[4][4][4];
    #pragma unroll
    for (int i = 0; i < 4; i++)
        #pragma unroll
        for (int j = 0; j < 4; j++)
            #pragma unroll
            for (int r = 0; r < 4; r++) cf[i][j][r] = 0.f;

    const int NCH = K / BK;          // 40

    float4 ra[4], rb[4];

    // ---- prefetch chunk 0 ----
    #pragma unroll
    for (int i = 0; i < 4; i++) {
        const int f = tid + 256 * i;
        const int m  = f >> 3, kq = f & 7;
        ra[i] = *reinterpret_cast<const float4*>(Aeff + (size_t)(m0 + m) * K + kq * 4);
        const int kk = f >> 5, nq = f & 31;
        rb[i] = *reinterpret_cast<const float4*>(W + (size_t)kk * N + n0 + nq * 4);
    }

    for (int c = 0; c < NCH; c++) {
        const int p = c & 1;
        float* As = sm + p * STG;
        float* Bs = As + ASZ;

        // ---- cvt + STS prefetched chunk c ----
        #pragma unroll
        for (int i = 0; i < 4; i++) {
            const int f = tid + 256 * i;
            const int m  = f >> 3, kq = f & 7;
            uint4 ua = { f2tf32(ra[i].x), f2tf32(ra[i].y), f2tf32(ra[i].z), f2tf32(ra[i].w) };
            *reinterpret_cast<uint4*>(As + m * PA + kq * 4) = ua;
            const int kk = f >> 5, nq = f & 31;
            uint4 ub = { f2tf32(rb[i].x), f2tf32(rb[i].y), f2tf32(rb[i].z), f2tf32(rb[i].w) };
            *reinterpret_cast<uint4*>(Bs + kk * PB + nq * 4) = ub;
        }
        __syncthreads();

        // ---- prefetch chunk c+1 (overlaps with MMA below) ----
        if (c + 1 < NCH) {
            const int k0 = (c + 1) * BK;
            #pragma unroll
            for (int i = 0; i < 4; i++) {
                const int f = tid + 256 * i;
                const int m  = f >> 3, kq = f & 7;
                ra[i] = *reinterpret_cast<const float4*>(
                    Aeff + (size_t)(m0 + m) * K + k0 + kq * 4);
                const int kk = f >> 5, nq = f & 31;
                rb[i] = *reinterpret_cast<const float4*>(
                    W + (size_t)(k0 + kk) * N + n0 + nq * 4);
            }
        }

        // ---- compute chunk c: 4 k-steps of m16n8k8 ----
        const uint32_t* Au = reinterpret_cast<const uint32_t*>(As);
        const uint32_t* Bu = reinterpret_cast<const uint32_t*>(Bs);
        #pragma unroll
        for (int ks = 0; ks < 4; ks++) {
            uint32_t af[4][4], bf[4][2];
            #pragma unroll
            for (int im = 0; im < 4; im++) {
                const int row = wm * 64 + im * 16 + g;
                const int col = ks * 8 + t;
                af[im][0] = Au[row * PA + col];
                af[im][1] = Au[(row + 8) * PA + col];
                af[im][2] = Au[row * PA + col + 4];
                af[im][3] = Au[(row + 8) * PA + col + 4];
            }
            #pragma unroll
            for (int in = 0; in < 4; in++) {
                const int ncol = wn * 32 + in * 8 + g;
                const int kk   = ks * 8 + t;
                bf[in][0] = Bu[kk * PB + ncol];
                bf[in][1] = Bu[(kk + 4) * PB + ncol];
            }
            #pragma unroll
            for (int im = 0; im < 4; im++)
                #pragma unroll
                for (int in = 0; in < 4; in++)
                    mma_tf32(cf[im][in], af[im][0], af[im][1], af[im][2], af[im][3],
                             bf[in][0], bf[in][1]);
        }
        __syncthreads();
    }

    // ---- epilogue: +bias, float2 stores (pairs never straddle head bounds) ----
    #pragma unroll
    for (int im = 0; im < 4; im++) {
        #pragma unroll
        for (int in = 0; in < 4; in++) {
            const int mrow0 = m0 + wm * 64 + im * 16 + g;
            const int ncol  = n0 + wn * 32 + in * 8 + 2 * t;
            const float2 bb = *reinterpret_cast<const float2*>(bias + ncol);
            #pragma unroll
            for (int h2 = 0; h2 < 2; h2++) {           // row and row+8
                const int m = mrow0 + h2 * 8;
                float2 v;
                v.x = cf[im][in][h2 * 2 + 0] + bb.x;
                v.y = cf[im][in][h2 * 2 + 1] + bb.y;
                if (MODE == 0) {
                    const int b = m >> 10;
                    const int s = m & 1023;
                    const int which = ncol / CD;        // 0=q 1=k 2=v
                    const int r = ncol - which * CD;
                    const int h = r / CHD;
                    const int d = r - h * CHD;
                    const size_t di = ((size_t)(b * CH + h) * CS + s) * CHD + d;
                    float* dst = (which == 0) ? g_q : (which == 1) ? g_k : g_v;
                    *reinterpret_cast<float2*>(dst + di) = v;
                } else {
                    *reinterpret_cast<float2*>(out + (size_t)m * CD + ncol) = v;
                }
            }
        }
    }
}

// ============================================================================
// RoPE (half-rotation): one thread per (b,h,s, d<40) pair; applies to q and k.
// ============================================================================
__global__ void __launch_bounds__(256)
rope_kernel(const float* __restrict__ cosb, const float* __restrict__ sinb)
{
    const int idx = blockIdx.x * blockDim.x + threadIdx.x;
    constexpr int TOT = CB * CH * CS * (CHD / 2);
    if (idx >= TOT) return;
    const int d  = idx % (CHD / 2);
    const int s  = (idx / (CHD / 2)) % CS;
    const int bh = idx / ((CHD / 2) * CS);

    const float c  = cosb[s * CHD + d];
    const float sn = sinb[s * CHD + d];
    const size_t base = ((size_t)bh * CS + s) * CHD;

    float q1 = g_q[base + d], q2 = g_q[base + d + 40];
    g_q[base + d]      = q1 * c - q2 * sn;
    g_q[base + d + 40] = q2 * c + q1 * sn;

    float k1 = g_k[base + d], k2 = g_k[base + d + 40];
    g_k[base + d]      = k1 * c - k2 * sn;
    g_k[base + d + 40] = k2 * c + k1 * sn;
}

// ============================================================================
// Fused flash attention (fp32 SIMT; tensor-core port is the next lever).
// grid (S/64, B*H), 256 threads. Writes g_ctx[b, s, h*80+d].
// ============================================================================
__global__ void __launch_bounds__(256)
attn_kernel()
{
    extern __shared__ float smf[];
    float* Qt = smf;                       // [80][68]  d-major, *SCALE applied
    float* Kt = Qt + 80 * 68;              // [80][68]  d-major
    float* Vs = Kt + 80 * 68;              // [64][81]  row-major
    float* Ps = Vs + 64 * 81;              // [64][68]

    const int tid = threadIdx.x;
    const int tx  = tid & 15;
    const int ty  = tid >> 4;
    const int bh  = blockIdx.y;
    const int q0  = blockIdx.x * 64;

    const float* __restrict__ Qg = g_q + (size_t)bh * CS * CHD;
    const float* __restrict__ Kg = g_k + (size_t)bh * CS * CHD;
    const float* __restrict__ Vg = g_v + (size_t)bh * CS * CHD;

    for (int p = tid; p < 64 * CHD; p += 256) {
        const int r = p / CHD, c = p - r * CHD;
        Qt[c * 68 + r] = Qg[(size_t)(q0 + r) * CHD + c] * ATTN_SCALE;
    }

    float m_[4], l_[4], o_[4][5];
    #pragma unroll
    for (int i = 0; i < 4; i++) {
        m_[i] = -1e30f; l_[i] = 0.f;
        #pragma unroll
        for (int c = 0; c < 5; c++) o_[i][c] = 0.f;
    }

    for (int tt = 0; tt < CS; tt += 64) {
        __syncthreads();
        for (int p = tid; p < 64 * CHD; p += 256) {
            const int r = p / CHD, c = p - r * CHD;
            Kt[c * 68 + r]  = Kg[(size_t)(tt + r) * CHD + c];
            Vs[r * 81 + c]  = Vg[(size_t)(tt + r) * CHD + c];
        }
        __syncthreads();

        float sacc[4][4] = {};
        #pragma unroll 8
        for (int d = 0; d < CHD; d++) {
            float4 a4 = *reinterpret_cast<const float4*>(&Qt[d * 68 + ty * 4]);
            float4 b4 = *reinterpret_cast<const float4*>(&Kt[d * 68 + tx * 4]);
            float a[4] = {a4.x, a4.y, a4.z, a4.w};
            float b[4] = {b4.x, b4.y, b4.z, b4.w};
            #pragma unroll
            for (int i = 0; i < 4; i++)
                #pragma unroll
                for (int j = 0; j < 4; j++)
                    sacc[i][j] += a[i] * b[j];
        }

        #pragma unroll
        for (int i = 0; i < 4; i++) {
            float mx = fmaxf(fmaxf(sacc[i][0], sacc[i][1]),
                             fmaxf(sacc[i][2], sacc[i][3]));
            #pragma unroll
            for (int off = 8; off >= 1; off >>= 1)
                mx = fmaxf(mx, __shfl_xor_sync(0xffffffffu, mx, off));
            const float mnew = fmaxf(m_[i], mx);
            const float alpha = __expf(m_[i] - mnew);
            float rs = 0.f;
            #pragma unroll
            for (int j = 0; j < 4; j++) {
                const float p = __expf(sacc[i][j] - mnew);
                sacc[i][j] = p;
                rs += p;
            }
            #pragma unroll
            for (int off = 8; off >= 1; off >>= 1)
                rs += __shfl_xor_sync(0xffffffffu, rs, off);
            l_[i] = l_[i] * alpha + rs;
            m_[i] = mnew;
            #pragma unroll
            for (int c = 0; c < 5; c++) o_[i][c] *= alpha;
            float4 pv = make_float4(sacc[i][0], sacc[i][1], sacc[i][2], sacc[i][3]);
            *reinterpret_cast<float4*>(&Ps[(ty * 4 + i) * 68 + tx * 4]) = pv;
        }
        __syncthreads();

        #pragma unroll 4
        for (int j = 0; j < 64; j++) {
            float pr[4], vv[5];
            #pragma unroll
            for (int i = 0; i < 4; i++) pr[i] = Ps[(ty * 4 + i) * 68 + j];
            #pragma unroll
            for (int c = 0; c < 5; c++) vv[c] = Vs[j * 81 + tx * 5 + c];
            #pragma unroll
            for (int i = 0; i < 4; i++)
                #pragma unroll
                for (int c = 0; c < 5; c++)
                    o_[i][c] += pr[i] * vv[c];
        }
    }

    const int b = bh / CH, h = bh - b * CH;
    #pragma unroll
    for (int i = 0; i < 4; i++) {
        const int srow = q0 + ty * 4 + i;
        const float inv = 1.f / l_[i];
        #pragma unroll
        for (int c = 0; c < 5; c++)
            g_ctx[((size_t)b * CS + srow) * CD + h * CHD + tx * 5 + c] = o_[i][c] * inv;
    }
}

// ============================================================================
// launch
// ============================================================================
extern "C" void kernel_launch(void* const* d_in, const int* in_sizes, int n_in,
                              void* d_out, int out_size)
{
    const float* x        = (const float*)d_in[0];
    const float* rope_cos = (const float*)d_in[1];
    const float* rope_sin = (const float*)d_in[2];
    const float* Wqkv     = (const float*)d_in[3];
    const float* bqkv     = (const float*)d_in[4];
    const float* Wproj    = (const float*)d_in[5];
    const float* bproj    = (const float*)d_in[6];
    float* out            = (float*)d_out;

    // 1) QKV projection (tf32 mma.sync) -> g_q/g_k/g_v
    cudaFuncSetAttribute(gemm_tc<0>, cudaFuncAttributeMaxDynamicSharedMemorySize, GEMM_SMEM);
    gemm_tc<0><<<dim3(CNQKV / BN, CM / BM), 256, GEMM_SMEM>>>(x, Wqkv, bqkv, nullptr, CNQKV, CD);

    // 2) RoPE on q,k
    {
        const int pairs = CB * CH * CS * (CHD / 2);
        rope_kernel<<<(pairs + 255) / 256, 256>>>(rope_cos, rope_sin);
    }

    // 3) fused flash attention -> g_ctx
    {
        const int smem = (80 * 68 * 2 + 64 * 81 + 64 * 68) * (int)sizeof(float); // 81,664 B
        cudaFuncSetAttribute(attn_kernel, cudaFuncAttributeMaxDynamicSharedMemorySize, smem);
        attn_kernel<<<dim3(CS / 64, CB * CH), 256, smem>>>();
    }

    // 4) output projection (tf32 mma.sync) -> d_out
    cudaFuncSetAttribute(gemm_tc<1>, cudaFuncAttributeMaxDynamicSharedMemorySize, GEMM_SMEM);
    gemm_tc<1><<<dim3(CD / BN, CM / BM), 256, GEMM_SMEM>>>(nullptr, Wproj, bproj, out, CD, CD);
}

// round 5
// speedup vs baseline: 2.4726x; 1.4431x over previous
#include <cuda_runtime.h>
#include <cstdint>

// ---------------- problem constants ----------------
namespace {
constexpr int CB  = 4;      // batch
constexpr int CS  = 1024;   // seq
constexpr int CD  = 1280;   // model dim
constexpr int CH  = 16;     // heads
constexpr int CHD = 80;     // head dim
constexpr int CM  = CB * CS;          // 4096 rows
constexpr int CNQKV = 3 * CD;         // 3840

// dense GEMM tiling
constexpr int BM = 128, BN = 128, BK = 32;
constexpr int PA = 36;    // A smem pitch (floats): 4g+t conflict-free
constexpr int PB = 136;   // B smem pitch (floats): 8t+g conflict-free
constexpr int ASZ = BM * PA;
constexpr int BSZ = BK * PB;
constexpr int STG = ASZ + BSZ;
constexpr int GEMM_SMEM = 2 * STG * 4;  // 71680 bytes

// attention smem pitches (u32 units)
constexpr int PQ = 84;   // Qs [64][80]: A-frag lane bank = 20g+t  (bijective mod 32)
constexpr int PK = 72;   // Kt [80][64]: B-frag lane bank = 8t+g   (bijective)
constexpr int PV = 88;   // Vs [64][80]: B-frag lane bank = 24t+g  (bijective)
constexpr int PP = 68;   // Ps [64][64]: A-frag lane bank = 4g+t   (bijective)
constexpr int ATTN_U32 = 64*PQ + 80*PK + 64*PV + 64*PP + 128;
constexpr int ATTN_SMEM = ATTN_U32 * 4;   // 84,992 B
}
#define ATTN_SCALE 0.11180339887498948f  // 80^-0.5

// ---------------- scratch (device globals; no allocs allowed) ----------------
__device__ __align__(16) float g_q[CB * CH * CS * CHD];     // [b,h,s,d]
__device__ __align__(16) float g_k[CB * CH * CS * CHD];
__device__ __align__(16) float g_v[CB * CH * CS * CHD];
__device__ __align__(16) float g_ctx[CM * CD];              // [b,s, h*HD+d]

// ---------------- tf32 helpers (plain sm_103-safe PTX) ----------------
__device__ __forceinline__ uint32_t f2tf32(float f) {
    uint32_t u;
    asm("cvt.rna.tf32.f32 %0, %1;" : "=r"(u) : "f"(f));
    return u;
}
__device__ __forceinline__ void mma_tf32(float c[4],
                                         uint32_t a0, uint32_t a1, uint32_t a2, uint32_t a3,
                                         uint32_t b0, uint32_t b1) {
    asm volatile(
        "mma.sync.aligned.m16n8k8.row.col.f32.tf32.tf32.f32 "
        "{%0,%1,%2,%3}, {%4,%5,%6,%7}, {%8,%9}, {%0,%1,%2,%3};"
        : "+f"(c[0]), "+f"(c[1]), "+f"(c[2]), "+f"(c[3])
        : "r"(a0), "r"(a1), "r"(a2), "r"(a3), "r"(b0), "r"(b1));
}

// ============================================================================
// tf32 mma.sync GEMM (unchanged from R4): C(128x128) = A @ W + bias
// ============================================================================
template <int MODE>
__global__ void __launch_bounds__(256)
gemm_tc(const float* __restrict__ A, const float* __restrict__ W,
        const float* __restrict__ bias, float* __restrict__ out,
        int N, int K)
{
    extern __shared__ float sm[];

    const float* __restrict__ Aeff = (MODE == 1) ? (const float*)g_ctx : A;

    const int tid  = threadIdx.x;
    const int wid  = tid >> 5;
    const int lane = tid & 31;
    const int g    = lane >> 2;
    const int t    = lane & 3;
    const int wm   = wid & 1;
    const int wn   = wid >> 1;
    const int m0   = blockIdx.y * BM;
    const int n0   = blockIdx.x * BN;

    float cf[4][4][4];
    #pragma unroll
    for (int i = 0; i < 4; i++)
        #pragma unroll
        for (int j = 0; j < 4; j++)
            #pragma unroll
            for (int r = 0; r < 4; r++) cf[i][j][r] = 0.f;

    const int NCH = K / BK;

    float4 ra[4], rb[4];

    #pragma unroll
    for (int i = 0; i < 4; i++) {
        const int f = tid + 256 * i;
        const int m  = f >> 3, kq = f & 7;
        ra[i] = *reinterpret_cast<const float4*>(Aeff + (size_t)(m0 + m) * K + kq * 4);
        const int kk = f >> 5, nq = f & 31;
        rb[i] = *reinterpret_cast<const float4*>(W + (size_t)kk * N + n0 + nq * 4);
    }

    for (int c = 0; c < NCH; c++) {
        const int p = c & 1;
        float* As = sm + p * STG;
        float* Bs = As + ASZ;

        #pragma unroll
        for (int i = 0; i < 4; i++) {
            const int f = tid + 256 * i;
            const int m  = f >> 3, kq = f & 7;
            uint4 ua = { f2tf32(ra[i].x), f2tf32(ra[i].y), f2tf32(ra[i].z), f2tf32(ra[i].w) };
            *reinterpret_cast<uint4*>(As + m * PA + kq * 4) = ua;
            const int kk = f >> 5, nq = f & 31;
            uint4 ub = { f2tf32(rb[i].x), f2tf32(rb[i].y), f2tf32(rb[i].z), f2tf32(rb[i].w) };
            *reinterpret_cast<uint4*>(Bs + kk * PB + nq * 4) = ub;
        }
        __syncthreads();

        if (c + 1 < NCH) {
            const int k0 = (c + 1) * BK;
            #pragma unroll
            for (int i = 0; i < 4; i++) {
                const int f = tid + 256 * i;
                const int m  = f >> 3, kq = f & 7;
                ra[i] = *reinterpret_cast<const float4*>(
                    Aeff + (size_t)(m0 + m) * K + k0 + kq * 4);
                const int kk = f >> 5, nq = f & 31;
                rb[i] = *reinterpret_cast<const float4*>(
                    W + (size_t)(k0 + kk) * N + n0 + nq * 4);
            }
        }

        const uint32_t* Au = reinterpret_cast<const uint32_t*>(As);
        const uint32_t* Bu = reinterpret_cast<const uint32_t*>(Bs);
        #pragma unroll
        for (int ks = 0; ks < 4; ks++) {
            uint32_t af[4][4], bf[4][2];
            #pragma unroll
            for (int im = 0; im < 4; im++) {
                const int row = wm * 64 + im * 16 + g;
                const int col = ks * 8 + t;
                af[im][0] = Au[row * PA + col];
                af[im][1] = Au[(row + 8) * PA + col];
                af[im][2] = Au[row * PA + col + 4];
                af[im][3] = Au[(row + 8) * PA + col + 4];
            }
            #pragma unroll
            for (int in = 0; in < 4; in++) {
                const int ncol = wn * 32 + in * 8 + g;
                const int kk   = ks * 8 + t;
                bf[in][0] = Bu[kk * PB + ncol];
                bf[in][1] = Bu[(kk + 4) * PB + ncol];
            }
            #pragma unroll
            for (int im = 0; im < 4; im++)
                #pragma unroll
                for (int in = 0; in < 4; in++)
                    mma_tf32(cf[im][in], af[im][0], af[im][1], af[im][2], af[im][3],
                             bf[in][0], bf[in][1]);
        }
        __syncthreads();
    }

    #pragma unroll
    for (int im = 0; im < 4; im++) {
        #pragma unroll
        for (int in = 0; in < 4; in++) {
            const int mrow0 = m0 + wm * 64 + im * 16 + g;
            const int ncol  = n0 + wn * 32 + in * 8 + 2 * t;
            const float2 bb = *reinterpret_cast<const float2*>(bias + ncol);
            #pragma unroll
            for (int h2 = 0; h2 < 2; h2++) {
                const int m = mrow0 + h2 * 8;
                float2 v;
                v.x = cf[im][in][h2 * 2 + 0] + bb.x;
                v.y = cf[im][in][h2 * 2 + 1] + bb.y;
                if (MODE == 0) {
                    const int b = m >> 10;
                    const int s = m & 1023;
                    const int which = ncol / CD;
                    const int r = ncol - which * CD;
                    const int h = r / CHD;
                    const int d = r - h * CHD;
                    const size_t di = ((size_t)(b * CH + h) * CS + s) * CHD + d;
                    float* dst = (which == 0) ? g_q : (which == 1) ? g_k : g_v;
                    *reinterpret_cast<float2*>(dst + di) = v;
                } else {
                    *reinterpret_cast<float2*>(out + (size_t)m * CD + ncol) = v;
                }
            }
        }
    }
}

// ============================================================================
// RoPE (half-rotation), unchanged.
// ============================================================================
__global__ void __launch_bounds__(256)
rope_kernel(const float* __restrict__ cosb, const float* __restrict__ sinb)
{
    const int idx = blockIdx.x * blockDim.x + threadIdx.x;
    constexpr int TOT = CB * CH * CS * (CHD / 2);
    if (idx >= TOT) return;
    const int d  = idx % (CHD / 2);
    const int s  = (idx / (CHD / 2)) % CS;
    const int bh = idx / ((CHD / 2) * CS);

    const float c  = cosb[s * CHD + d];
    const float sn = sinb[s * CHD + d];
    const size_t base = ((size_t)bh * CS + s) * CHD;

    float q1 = g_q[base + d], q2 = g_q[base + d + 40];
    g_q[base + d]      = q1 * c - q2 * sn;
    g_q[base + d + 40] = q2 * c + q1 * sn;

    float k1 = g_k[base + d], k2 = g_k[base + d + 40];
    g_k[base + d]      = k1 * c - k2 * sn;
    g_k[base + d + 40] = k2 * c + k1 * sn;
}

// ============================================================================
// Fused flash attention, tf32 mma.sync.
// grid (S/64, B*H), 256 threads (8 warps).
// S-phase warps: 2(m:32) x 4(n:16).  PV-phase warps: 4(q:16) x 2(d:40).
// Online softmax SIMT on Ps (fp32 scores -> tf32 probs in-place).
// ============================================================================
__global__ void __launch_bounds__(256)
attn_tc()
{
    extern __shared__ uint32_t smu[];
    uint32_t* Qs = smu;                    // [64][PQ] tf32, pre-scaled
    uint32_t* Kt = Qs + 64 * PQ;           // [80][PK] tf32 (d-major)
    uint32_t* Vs = Kt + 80 * PK;           // [64][PV] tf32
    float*    Ps = (float*)(Vs + 64 * PV); // [64][PP] fp32 scores / tf32 probs
    float*    sAlpha = Ps + 64 * PP;       // [64]
    float*    sL     = sAlpha + 64;        // [64]

    const int tid  = threadIdx.x;
    const int wid  = tid >> 5;
    const int lane = tid & 31;
    const int g    = lane >> 2;
    const int t    = lane & 3;
    const int wm   = wid & 1;    // S-phase
    const int wn   = wid >> 1;
    const int wq   = wid & 3;    // PV-phase
    const int wd   = wid >> 2;
    const int srow = tid >> 2;   // softmax row
    const int sseg = tid & 3;    // softmax 16-col segment

    const int bh = blockIdx.y;
    const int q0 = blockIdx.x * 64;

    const float* __restrict__ Qg = g_q + (size_t)bh * CS * CHD;
    const float* __restrict__ Kg = g_k + (size_t)bh * CS * CHD;
    const float* __restrict__ Vg = g_v + (size_t)bh * CS * CHD;

    // Q fill (once): tf32(q * SCALE)
    for (int p = tid; p < 64 * CHD; p += 256) {
        const int r = p / CHD, c = p - r * CHD;
        Qs[r * PQ + c] = f2tf32(Qg[(size_t)(q0 + r) * CHD + c] * ATTN_SCALE);
    }

    float m_ = -1e30f, l_ = 0.f;   // per softmax-row state (4 lanes share a row)
    float of[5][4];
    #pragma unroll
    for (int i = 0; i < 5; i++)
        #pragma unroll
        for (int r = 0; r < 4; r++) of[i][r] = 0.f;

    for (int tt = 0; tt < CS; tt += 64) {
        __syncthreads();   // prev PV done reading Ps/Vs; Q ready on first iter
        for (int p = tid; p < 64 * CHD; p += 256) {
            const int r = p / CHD, c = p - r * CHD;
            Kt[c * PK + r] = f2tf32(Kg[(size_t)(tt + r) * CHD + c]);
            Vs[r * PV + c] = f2tf32(Vg[(size_t)(tt + r) * CHD + c]);
        }
        __syncthreads();

        // ---- S = Q K^T (64x64), warp tile 32x16, 10 k8 steps ----
        float sacc[2][2][4];
        #pragma unroll
        for (int im = 0; im < 2; im++)
            #pragma unroll
            for (int in = 0; in < 2; in++)
                #pragma unroll
                for (int r = 0; r < 4; r++) sacc[im][in][r] = 0.f;

        #pragma unroll
        for (int ks = 0; ks < 10; ks++) {
            uint32_t af[2][4], bf[2][2];
            #pragma unroll
            for (int im = 0; im < 2; im++) {
                const int row = wm * 32 + im * 16 + g;
                const int col = ks * 8 + t;
                af[im][0] = Qs[row * PQ + col];
                af[im][1] = Qs[(row + 8) * PQ + col];
                af[im][2] = Qs[row * PQ + col + 4];
                af[im][3] = Qs[(row + 8) * PQ + col + 4];
            }
            #pragma unroll
            for (int in = 0; in < 2; in++) {
                const int n = wn * 16 + in * 8 + g;
                bf[in][0] = Kt[(ks * 8 + t) * PK + n];
                bf[in][1] = Kt[(ks * 8 + t + 4) * PK + n];
            }
            #pragma unroll
            for (int im = 0; im < 2; im++)
                #pragma unroll
                for (int in = 0; in < 2; in++)
                    mma_tf32(sacc[im][in], af[im][0], af[im][1], af[im][2], af[im][3],
                             bf[in][0], bf[in][1]);
        }
        // store S tile (fp32)
        #pragma unroll
        for (int im = 0; im < 2; im++) {
            const int r0 = wm * 32 + im * 16;
            #pragma unroll
            for (int in = 0; in < 2; in++) {
                const int cl = wn * 16 + in * 8 + 2 * t;
                *reinterpret_cast<float2*>(&Ps[(r0 + g) * PP + cl]) =
                    make_float2(sacc[im][in][0], sacc[im][in][1]);
                *reinterpret_cast<float2*>(&Ps[(r0 + g + 8) * PP + cl]) =
                    make_float2(sacc[im][in][2], sacc[im][in][3]);
            }
        }
        __syncthreads();

        // ---- online softmax: row srow, cols [sseg*16, sseg*16+16) ----
        {
            float* prow = Ps + srow * PP + sseg * 16;
            float vals[16];
            float mx = -1e30f;
            #pragma unroll
            for (int j = 0; j < 16; j++) { vals[j] = prow[j]; mx = fmaxf(mx, vals[j]); }
            mx = fmaxf(mx, __shfl_xor_sync(0xffffffffu, mx, 1));
            mx = fmaxf(mx, __shfl_xor_sync(0xffffffffu, mx, 2));
            const float mnew  = fmaxf(m_, mx);
            const float alpha = __expf(m_ - mnew);
            float rs = 0.f;
            uint32_t* prow_u = reinterpret_cast<uint32_t*>(prow);
            #pragma unroll
            for (int j = 0; j < 16; j++) {
                const float pj = __expf(vals[j] - mnew);
                rs += pj;
                prow_u[j] = f2tf32(pj);
            }
            rs += __shfl_xor_sync(0xffffffffu, rs, 1);
            rs += __shfl_xor_sync(0xffffffffu, rs, 2);
            l_ = l_ * alpha + rs;
            m_ = mnew;
            if (sseg == 0) sAlpha[srow] = alpha;
        }
        __syncthreads();

        // ---- O = O*alpha + P @ V, warp tile 16x40 (5 n8 atoms), 8 k8 steps ----
        {
            const float aL = sAlpha[wq * 16 + g];
            const float aH = sAlpha[wq * 16 + g + 8];
            #pragma unroll
            for (int in = 0; in < 5; in++) {
                of[in][0] *= aL; of[in][1] *= aL;
                of[in][2] *= aH; of[in][3] *= aH;
            }
            const uint32_t* Pu = reinterpret_cast<const uint32_t*>(Ps);
            #pragma unroll
            for (int ks = 0; ks < 8; ks++) {
                const int row = wq * 16 + g;
                const int col = ks * 8 + t;
                uint32_t a0 = Pu[row * PP + col];
                uint32_t a1 = Pu[(row + 8) * PP + col];
                uint32_t a2 = Pu[row * PP + col + 4];
                uint32_t a3 = Pu[(row + 8) * PP + col + 4];
                #pragma unroll
                for (int in = 0; in < 5; in++) {
                    const int n = wd * 40 + in * 8 + g;
                    const uint32_t b0 = Vs[(ks * 8 + t) * PV + n];
                    const uint32_t b1 = Vs[(ks * 8 + t + 4) * PV + n];
                    mma_tf32(of[in], a0, a1, a2, a3, b0, b1);
                }
            }
        }
    }

    // ---- epilogue ----
    __syncthreads();
    if (sseg == 0) sL[srow] = l_;
    __syncthreads();

    const int b = bh >> 4, h = bh & 15;
    const float invL = 1.f / sL[wq * 16 + g];
    const float invH = 1.f / sL[wq * 16 + g + 8];
    const int rL = q0 + wq * 16 + g;
    const int rH = rL + 8;
    #pragma unroll
    for (int in = 0; in < 5; in++) {
        const int col = h * CHD + wd * 40 + in * 8 + 2 * t;
        *reinterpret_cast<float2*>(&g_ctx[((size_t)b * CS + rL) * CD + col]) =
            make_float2(of[in][0] * invL, of[in][1] * invL);
        *reinterpret_cast<float2*>(&g_ctx[((size_t)b * CS + rH) * CD + col]) =
            make_float2(of[in][2] * invH, of[in][3] * invH);
    }
}

// ============================================================================
// launch
// ============================================================================
extern "C" void kernel_launch(void* const* d_in, const int* in_sizes, int n_in,
                              void* d_out, int out_size)
{
    const float* x        = (const float*)d_in[0];
    const float* rope_cos = (const float*)d_in[1];
    const float* rope_sin = (const float*)d_in[2];
    const float* Wqkv     = (const float*)d_in[3];
    const float* bqkv     = (const float*)d_in[4];
    const float* Wproj    = (const float*)d_in[5];
    const float* bproj    = (const float*)d_in[6];
    float* out            = (float*)d_out;

    // 1) QKV projection (tf32 mma.sync) -> g_q/g_k/g_v
    cudaFuncSetAttribute(gemm_tc<0>, cudaFuncAttributeMaxDynamicSharedMemorySize, GEMM_SMEM);
    gemm_tc<0><<<dim3(CNQKV / BN, CM / BM), 256, GEMM_SMEM>>>(x, Wqkv, bqkv, nullptr, CNQKV, CD);

    // 2) RoPE on q,k
    {
        const int pairs = CB * CH * CS * (CHD / 2);
        rope_kernel<<<(pairs + 255) / 256, 256>>>(rope_cos, rope_sin);
    }

    // 3) fused flash attention (tf32 mma.sync) -> g_ctx
    cudaFuncSetAttribute(attn_tc, cudaFuncAttributeMaxDynamicSharedMemorySize, ATTN_SMEM);
    attn_tc<<<dim3(CS / 64, CB * CH), 256, ATTN_SMEM>>>();

    // 4) output projection (tf32 mma.sync) -> d_out
    cudaFuncSetAttribute(gemm_tc<1>, cudaFuncAttributeMaxDynamicSharedMemorySize, GEMM_SMEM);
    gemm_tc<1><<<dim3(CD / BN, CM / BM), 256, GEMM_SMEM>>>(nullptr, Wproj, bproj, out, CD, CD);
}